// round 3
// baseline (speedup 1.0000x reference)
#include <cuda_runtime.h>

#define BB 4
#define CC 128
#define HIN 512
#define WIN 512
#define HS 128
#define KPAD 4
#define HP 136
#define NG 4
#define CG 32
#define NOFF 81
#define EPSV 1e-8f

typedef unsigned long long u64;

// ---------------- f32x2 helpers (sm_103a packed fp32) -----------------------
__device__ __forceinline__ u64 pk2(float lo, float hi) {
    u64 r; asm("mov.b64 %0,{%1,%2};" : "=l"(r) : "f"(lo), "f"(hi)); return r;
}
__device__ __forceinline__ void unpk2(u64 v, float& lo, float& hi) {
    asm("mov.b64 {%0,%1},%2;" : "=f"(lo), "=f"(hi) : "l"(v));
}
__device__ __forceinline__ u64 fma2(u64 a, u64 b, u64 c) {
    u64 d; asm("fma.rn.f32x2 %0,%1,%2,%3;" : "=l"(d) : "l"(a), "l"(b), "l"(c)); return d;
}
__device__ __forceinline__ u64 add2(u64 a, u64 b) {
    u64 d; asm("add.rn.f32x2 %0,%1,%2;" : "=l"(d) : "l"(a), "l"(b)); return d;
}

// ---------------- scratch ----------------------------------------------------
__device__ float g_xs[BB*CC*HS*HS];   // downsampled x
__device__ float g_yp[BB*CC*HP*HP];   // downsampled + reflect-pad y
__device__ float g_yc[BB*CC*HP*HP];   // conv output
__device__ float g_nx[BB*NG*HS*HS];   // max(||x||_g, eps)
__device__ float g_ny[BB*NG*HP*HP];   // ||yc||_g (raw)

// ---------------- bilinear downsample ---------------------------------------
__device__ __forceinline__ float bilin512(const float* __restrict__ p, int ti, int tj) {
    const double scale = 511.0 / 127.0;
    double py = ti * scale, px = tj * scale;
    int y0 = (int)py, x0 = (int)px;
    float fy = (float)(py - (double)y0);
    float fx = (float)(px - (double)x0);
    int y1 = min(y0 + 1, 511), x1 = min(x0 + 1, 511);
    const float* r0 = p + y0 * WIN;
    const float* r1 = p + y1 * WIN;
    float a = r0[x0], b = r0[x1], c = r1[x0], d = r1[x1];
    float top = a + (b - a) * fx;
    float bot = c + (d - c) * fx;
    return top + (bot - top) * fy;
}

__global__ void downsample_x_kernel(const float* __restrict__ x) {
    int idx = blockIdx.x * 256 + threadIdx.x;
    int j  = idx & 127;
    int i  = (idx >> 7) & 127;
    int bc = idx >> 14;
    const float* p = x + (size_t)bc * HIN * WIN;
    g_xs[idx] = bilin512(p, i, j);
}

__global__ void downsample_y_pad_kernel(const float* __restrict__ y) {
    int idx = blockIdx.x * 256 + threadIdx.x;
    if (idx >= BB*CC*HP*HP) return;
    int n  = idx % HP;
    int m  = (idx / HP) % HP;
    int bc = idx / (HP * HP);
    int t = m - KPAD; if (t < 0) t = -t; if (t > 127) t = 254 - t;
    int s = n - KPAD; if (s < 0) s = -s; if (s > 127) s = 254 - s;
    const float* p = y + (size_t)bc * HIN * WIN;
    g_yp[idx] = bilin512(p, t, s);
}

// ---------------- 3x3 conv via packed f32x2 ---------------------------------
// tile: 64 oc x 16h x 16w; 256 threads = 8 oc-threads x 32 px-threads
// thread: 8 oc x 8 px held as 8x4 f32x2 accumulators.
#define ICB 8
__global__ void __launch_bounds__(256, 2)
conv3x3_kernel(const float* __restrict__ Wt, const float* __restrict__ bias) {
    __shared__ __align__(16) float ins[ICB][18][20];  // even pitch -> aligned pairs
    __shared__ u64 ws2[ICB][9][64];                   // weights pre-duplicated {w,w}

    int bz  = blockIdx.z;
    int b   = bz >> 1;
    int oc0 = (bz & 1) * 64;
    int m0  = blockIdx.y * 16;
    int n0  = blockIdx.x * 16;
    int tid = threadIdx.x;
    int pxt = tid & 31;
    int oct = tid >> 5;              // warp id -> weight LDS broadcast
    int ti  = pxt >> 1;
    int tjb = (pxt & 1) * 8;

    u64 acc2[8][4];
    #pragma unroll
    for (int r = 0; r < 8; r++)
        #pragma unroll
        for (int k = 0; k < 4; k++) acc2[r][k] = 0ULL;

    const float* yp_b = g_yp + (size_t)b * CC * HP * HP;

    for (int ic0 = 0; ic0 < CC; ic0 += ICB) {
        __syncthreads();
        // input tile ICB x 18 x 18 (+-1 zero pad)
        for (int e = tid; e < ICB * 18 * 18; e += 256) {
            int col = e % 18;
            int row = (e / 18) % 18;
            int ic  = e / (18 * 18);
            int mm = m0 - 1 + row, nn = n0 - 1 + col;
            float v = 0.f;
            if (mm >= 0 && mm < HP && nn >= 0 && nn < HP)
                v = yp_b[(size_t)(ic0 + ic) * HP * HP + mm * HP + nn];
            ins[ic][row][col] = v;
        }
        // weights duplicated into f32x2
        for (int e = tid; e < 64 * ICB * 9; e += 256) {
            int ocl = e / (ICB * 9);
            int r   = e % (ICB * 9);
            float v = Wt[(size_t)(oc0 + ocl) * (CC * 9) + ic0 * 9 + r];
            ws2[r / 9][r % 9][ocl] = pk2(v, v);
        }
        __syncthreads();

        #pragma unroll 1
        for (int ic = 0; ic < ICB; ic++) {
            #pragma unroll
            for (int di = 0; di < 3; di++) {
                u64 E[5], O[4];
                const float* rowp = &ins[ic][ti + di][tjb];
                #pragma unroll
                for (int k = 0; k < 5; k++)
                    E[k] = *(const u64*)(rowp + 2 * k);       // aligned LDS.64
                #pragma unroll
                for (int k = 0; k < 4; k++) {
                    float l0, h0, l1, h1;
                    unpk2(E[k], l0, h0); unpk2(E[k + 1], l1, h1);
                    O[k] = pk2(h0, l1);                        // odd-offset pair
                }
                // dj = 0 : pairs E[0..3]
                #pragma unroll
                for (int r = 0; r < 8; r++) {
                    u64 wv = ws2[ic][di * 3 + 0][oct * 8 + r];
                    #pragma unroll
                    for (int k = 0; k < 4; k++)
                        acc2[r][k] = fma2(wv, E[k], acc2[r][k]);
                }
                // dj = 1 : pairs O[0..3]
                #pragma unroll
                for (int r = 0; r < 8; r++) {
                    u64 wv = ws2[ic][di * 3 + 1][oct * 8 + r];
                    #pragma unroll
                    for (int k = 0; k < 4; k++)
                        acc2[r][k] = fma2(wv, O[k], acc2[r][k]);
                }
                // dj = 2 : pairs E[1..4]
                #pragma unroll
                for (int r = 0; r < 8; r++) {
                    u64 wv = ws2[ic][di * 3 + 2][oct * 8 + r];
                    #pragma unroll
                    for (int k = 0; k < 4; k++)
                        acc2[r][k] = fma2(wv, E[k + 1], acc2[r][k]);
                }
            }
        }
    }

    int m  = m0 + ti;
    int nb = n0 + tjb;
    if (m < HP) {
        #pragma unroll
        for (int r = 0; r < 8; r++) {
            int oc = oc0 + oct * 8 + r;
            u64 bi2 = pk2(bias[oc], bias[oc]);
            float* outp = g_yc + ((size_t)b * CC + oc) * HP * HP + m * HP + nb;
            #pragma unroll
            for (int k = 0; k < 4; k++) {
                if (nb + 2 * k < HP)                   // HP even -> pair-granular
                    *(u64*)(outp + 2 * k) = add2(acc2[r][k], bi2);
            }
        }
    }
}

// ---------------- group norms ------------------------------------------------
__global__ void norm_x_kernel() {
    int idx = blockIdx.x * 256 + threadIdx.x;
    if (idx >= BB * NG * HS * HS) return;
    int px = idx % (HS * HS);
    int bg = idx / (HS * HS);
    int b = bg >> 2, g = bg & 3;
    const float* p = g_xs + ((size_t)b * CC + g * CG) * HS * HS + px;
    float s = 0.f;
    #pragma unroll
    for (int c = 0; c < CG; c++) { float v = p[(size_t)c * HS * HS]; s = fmaf(v, v, s); }
    g_nx[idx] = fmaxf(sqrtf(s), EPSV);
}

__global__ void norm_y_kernel() {
    int idx = blockIdx.x * 256 + threadIdx.x;
    if (idx >= BB * NG * HP * HP) return;
    int px = idx % (HP * HP);
    int bg = idx / (HP * HP);
    int b = bg >> 2, g = bg & 3;
    const float* p = g_yc + ((size_t)b * CC + g * CG) * HP * HP + px;
    float s = 0.f;
    #pragma unroll
    for (int c = 0; c < CG; c++) { float v = p[(size_t)c * HP * HP]; s = fmaf(v, v, s); }
    g_ny[idx] = sqrtf(s);
}

// ---------------- 81-offset correlation --------------------------------------
#define CORR_SY (CG * 16 * 40)
#define CORR_SN (16 * 40)
#define CORR_SMEM ((CORR_SY + CORR_SN) * 4)

__global__ void corr_kernel(float* __restrict__ out) {
    extern __shared__ float sm[];
    float* sy = sm;
    float* sn = sm + CORR_SY;

    int bg = blockIdx.z;
    int b  = bg >> 2, g = bg & 3;
    int i0 = blockIdx.y * 8;
    int j0 = blockIdx.x * 32;
    int tid = threadIdx.x;
    int tj = tid & 31, ti = tid >> 5;

    const float* ycb = g_yc + ((size_t)b * CC + g * CG) * HP * HP;
    for (int e = tid; e < CG * 16 * 40; e += 256) {
        int col = e % 40;
        int row = (e / 40) % 16;
        int c   = e / (16 * 40);
        sy[e] = ycb[(size_t)c * HP * HP + (i0 + row) * HP + (j0 + col)];
    }
    const float* nyb = g_ny + (size_t)bg * HP * HP;
    for (int e = tid; e < 16 * 40; e += 256) {
        int col = e % 40, row = e / 40;
        sn[e] = 1.0f / fmaxf(nyb[(i0 + row) * HP + (j0 + col)], EPSV);
    }
    __syncthreads();

    float xr[CG];
    const float* xsb = g_xs + ((size_t)b * CC + g * CG) * HS * HS
                            + (i0 + ti) * HS + (j0 + tj);
    #pragma unroll
    for (int c = 0; c < CG; c++) xr[c] = xsb[(size_t)c * HS * HS];

    float inx = 1.0f / g_nx[(size_t)bg * HS * HS + (i0 + ti) * HS + (j0 + tj)];
    float* outp = out + (size_t)bg * NOFF * HS * HS + (i0 + ti) * HS + (j0 + tj);

    #pragma unroll 1
    for (int oi = 0; oi < 9; oi++) {
        #pragma unroll 1
        for (int oj = 0; oj < 9; oj++) {
            float acc = 0.f;
            int base = (ti + oi) * 40 + tj + oj;
            #pragma unroll
            for (int c = 0; c < CG; c++)
                acc = fmaf(xr[c], sy[c * (16 * 40) + base], acc);
            float r = sn[base];
            outp[(size_t)(oi * 9 + oj) * (HS * HS)] = acc * inx * r;
        }
    }
}

// ---------------- launcher ----------------------------------------------------
extern "C" void kernel_launch(void* const* d_in, const int* in_sizes, int n_in,
                              void* d_out, int out_size) {
    const float* x     = (const float*)d_in[0];
    const float* y     = (const float*)d_in[1];
    const float* Wt    = (const float*)d_in[2];
    const float* bconv = (const float*)d_in[3];
    float* out = (float*)d_out;

    cudaFuncSetAttribute(corr_kernel,
                         cudaFuncAttributeMaxDynamicSharedMemorySize, CORR_SMEM);

    downsample_x_kernel<<<(BB*CC*HS*HS) / 256, 256>>>(x);
    downsample_y_pad_kernel<<<(BB*CC*HP*HP + 255) / 256, 256>>>(y);
    conv3x3_kernel<<<dim3(9, 9, BB * 2), 256>>>(Wt, bconv);
    norm_x_kernel<<<(BB*NG*HS*HS + 255) / 256, 256>>>();
    norm_y_kernel<<<(BB*NG*HP*HP + 255) / 256, 256>>>();
    corr_kernel<<<dim3(4, 16, BB * NG), 256, CORR_SMEM>>>(out);
}

// round 4
// speedup vs baseline: 1.5221x; 1.5221x over previous
#include <cuda_runtime.h>
#include <cuda_bf16.h>

#define BB 4
#define CC 128
#define HIN 512
#define WIN 512
#define HS 128
#define KPAD 4
#define HP 136            // yp / conv-output spatial size
#define HPP 138           // zero-padded plane dim
#define NPIX (HPP*HPP)    // 19044
#define PROW 19232        // padded plane row (u32 elems), covers over-reads
#define NG 4
#define CG 32
#define NOFF 81
#define EPSV 1e-8f

// ---------------- scratch ----------------------------------------------------
__device__ unsigned int g_Ppk[BB*CC*PROW];        // packed bf16: hi | lo<<16
__device__ __nv_bfloat16 g_wB_hi[8*CC*144];       // weights [icb][oc][144]
__device__ __nv_bfloat16 g_wB_lo[8*CC*144];
__device__ float g_xs[BB*CC*HS*HS];               // downsampled x
__device__ float g_yc[BB*CC*HP*HP];               // conv output
__device__ float g_nx[BB*NG*HS*HS];
__device__ float g_ny[BB*NG*HP*HP];

// ---------------- bilinear ----------------------------------------------------
__device__ __forceinline__ float bilin512(const float* __restrict__ p, int ti, int tj) {
    const double scale = 511.0 / 127.0;
    double py = ti * scale, px = tj * scale;
    int y0 = (int)py, x0 = (int)px;
    float fy = (float)(py - (double)y0);
    float fx = (float)(px - (double)x0);
    int y1 = min(y0 + 1, 511), x1 = min(x0 + 1, 511);
    const float* r0 = p + y0 * WIN;
    const float* r1 = p + y1 * WIN;
    float a = r0[x0], b = r0[x1], c = r1[x0], d = r1[x1];
    float top = a + (b - a) * fx;
    float bot = c + (d - c) * fx;
    return top + (bot - top) * fy;
}

__global__ void downsample_x_kernel(const float* __restrict__ x) {
    int idx = blockIdx.x * 256 + threadIdx.x;
    int j  = idx & 127;
    int i  = (idx >> 7) & 127;
    int bc = idx >> 14;
    const float* p = x + (size_t)bc * HIN * WIN;
    g_xs[idx] = bilin512(p, i, j);
}

// downsample y + reflect-pad(4) + zero-pad(1), flatten to 138x138 plane,
// split into bf16 hi/lo packed in one u32.
__global__ void make_P_kernel(const float* __restrict__ y) {
    int idx = blockIdx.x * 256 + threadIdx.x;
    if (idx >= BB*CC*PROW) return;
    int q  = idx % PROW;
    int bc = idx / PROW;
    float v = 0.f;
    if (q < NPIX) {
        int u = q / HPP, w = q % HPP;
        if (u > 0 && u < HPP-1 && w > 0 && w < HPP-1) {
            int m = (u - 1) - KPAD; if (m < 0) m = -m; if (m > 127) m = 254 - m;
            int n = (w - 1) - KPAD; if (n < 0) n = -n; if (n > 127) n = 254 - n;
            v = bilin512(y + (size_t)bc * HIN * WIN, m, n);
        }
    }
    __nv_bfloat16 h = __float2bfloat16(v);
    __nv_bfloat16 l = __float2bfloat16(v - __bfloat162float(h));
    unsigned int hu = (unsigned int)__bfloat16_as_ushort(h);
    unsigned int lu = (unsigned int)__bfloat16_as_ushort(l);
    g_Ppk[idx] = hu | (lu << 16);
}

// repack weights: g_wB[icb][oc][k], k = il*9 + di*3 + dj, ic = icb*16+il
__global__ void prep_w_kernel(const float* __restrict__ W) {
    int idx = blockIdx.x * 256 + threadIdx.x;
    if (idx >= 8*CC*144) return;
    int k   = idx % 144;
    int oc  = (idx / 144) % CC;
    int icb = idx / (144 * CC);
    int il = k / 9, r = k % 9, di = r / 3, dj = r % 3;
    int ic = icb * 16 + il;
    float w = W[((size_t)(oc * CC + ic) * 3 + di) * 3 + dj];
    __nv_bfloat16 h = __float2bfloat16(w);
    __nv_bfloat16 l = __float2bfloat16(w - __bfloat162float(h));
    g_wB_hi[idx] = h;
    g_wB_lo[idx] = l;
}

// ---------------- tensor-core conv (implicit GEMM) ---------------------------
#define APITCH 304        // bytes per smem row (144*2 pad to 304: conflict-free)
#define STAGE_W 408       // staging row length (u32)
#define SM_STG   0
#define SM_AHI   26112
#define SM_ALO   (SM_AHI + 128*APITCH)
#define SM_BHI   (SM_ALO + 128*APITCH)
#define SM_BLO   (SM_BHI + 128*APITCH)
#define CONV_SMEM (SM_BLO + 128*APITCH)   // 181760 B

__device__ __forceinline__ void ldsm4(unsigned* r, const void* p) {
    unsigned a = (unsigned)__cvta_generic_to_shared(p);
    asm volatile("ldmatrix.sync.aligned.m8n8.x4.shared.b16 {%0,%1,%2,%3},[%4];"
        : "=r"(r[0]), "=r"(r[1]), "=r"(r[2]), "=r"(r[3]) : "r"(a));
}
__device__ __forceinline__ void mma16816(float* c, const unsigned* a,
                                         unsigned b0, unsigned b1) {
    asm volatile(
        "mma.sync.aligned.m16n8k16.row.col.f32.bf16.bf16.f32 "
        "{%0,%1,%2,%3},{%4,%5,%6,%7},{%8,%9},{%0,%1,%2,%3};"
        : "+f"(c[0]), "+f"(c[1]), "+f"(c[2]), "+f"(c[3])
        : "r"(a[0]), "r"(a[1]), "r"(a[2]), "r"(a[3]), "r"(b0), "r"(b1));
}

__global__ void __launch_bounds__(256, 1)
conv_mma_kernel(const float* __restrict__ bias) {
    extern __shared__ char sm[];
    unsigned int* stg = (unsigned int*)(sm + SM_STG);
    char* AsHi = sm + SM_AHI;
    char* AsLo = sm + SM_ALO;
    char* BsHi = sm + SM_BHI;
    char* BsLo = sm + SM_BLO;

    int b  = blockIdx.y;
    int p0 = blockIdx.x * 128;
    int tid = threadIdx.x, lane = tid & 31, wid = tid >> 5;
    int wm = wid & 3, wn = wid >> 2;     // 4 m-warps x 2 n-warps

    float acc[2][8][4];
    #pragma unroll
    for (int mt = 0; mt < 2; mt++)
        #pragma unroll
        for (int nt = 0; nt < 8; nt++)
            #pragma unroll
            for (int r = 0; r < 4; r++) acc[mt][nt][r] = 0.f;

    #pragma unroll 1
    for (int icb = 0; icb < 8; icb++) {
        __syncthreads();
        // stage 16 plane rows (window of 408 u32)
        for (int e = tid; e < 16 * 102; e += 256) {
            int il = e / 102, jj = e % 102;
            uint4 v = *(const uint4*)(g_Ppk +
                (size_t)(b * CC + icb * 16 + il) * PROW + p0 + jj * 4);
            *(uint4*)(stg + il * STAGE_W + jj * 4) = v;
        }
        // weight tiles: 128 oc rows x 288B
        for (int e = tid; e < 128 * 18; e += 256) {
            int n = e / 18, s = e % 18;
            *(uint4*)(BsHi + n * APITCH + s * 16) =
                *(const uint4*)((const char*)(g_wB_hi + (size_t)(icb * 128 + n) * 144) + s * 16);
            *(uint4*)(BsLo + n * APITCH + s * 16) =
                *(const uint4*)((const char*)(g_wB_lo + (size_t)(icb * 128 + n) * 144) + s * 16);
        }
        __syncthreads();
        // im2col build: As[m][k], k = il*9 + di*3 + dj
        for (int e = tid; e < 128 * 16 * 3; e += 256) {
            int di = e % 3;
            int il = (e / 3) & 15;
            int m  = e / 48;
            int base = m + di * HPP;
            unsigned v0 = stg[il * STAGE_W + base];
            unsigned v1 = stg[il * STAGE_W + base + 1];
            unsigned v2 = stg[il * STAGE_W + base + 2];
            int kb = il * 9 + di * 3;
            unsigned short* ah = (unsigned short*)(AsHi + m * APITCH) + kb;
            unsigned short* al = (unsigned short*)(AsLo + m * APITCH) + kb;
            ah[0] = (unsigned short)v0; ah[1] = (unsigned short)v1; ah[2] = (unsigned short)v2;
            al[0] = (unsigned short)(v0 >> 16); al[1] = (unsigned short)(v1 >> 16);
            al[2] = (unsigned short)(v2 >> 16);
        }
        __syncthreads();

        #pragma unroll 1
        for (int ks = 0; ks < 9; ks++) {
            int colb = (ks * 16 + ((lane >> 4) << 3)) * 2;   // byte col for ldsm
            int ar   = wm * 32 + (lane & 15);
            unsigned ahi[2][4], alo[2][4];
            ldsm4(ahi[0], AsHi + ar * APITCH + colb);
            ldsm4(ahi[1], AsHi + (ar + 16) * APITCH + colb);
            ldsm4(alo[0], AsLo + ar * APITCH + colb);
            ldsm4(alo[1], AsLo + (ar + 16) * APITCH + colb);
            #pragma unroll
            for (int np = 0; np < 4; np++) {
                int nr = wn * 64 + np * 16 + (lane & 15);
                unsigned bh[4], bl[4];
                ldsm4(bh, BsHi + nr * APITCH + colb);
                ldsm4(bl, BsLo + nr * APITCH + colb);
                #pragma unroll
                for (int mt = 0; mt < 2; mt++) {
                    // n-tile np*2   : b0=bh[0], b1=bh[2]
                    mma16816(acc[mt][np*2],   ahi[mt], bh[0], bh[2]);
                    mma16816(acc[mt][np*2],   ahi[mt], bl[0], bl[2]);
                    mma16816(acc[mt][np*2],   alo[mt], bh[0], bh[2]);
                    // n-tile np*2+1 : b0=bh[1], b1=bh[3]
                    mma16816(acc[mt][np*2+1], ahi[mt], bh[1], bh[3]);
                    mma16816(acc[mt][np*2+1], ahi[mt], bl[1], bl[3]);
                    mma16816(acc[mt][np*2+1], alo[mt], bh[1], bh[3]);
                }
            }
        }
    }

    // epilogue: D[m][oc] -> g_yc planar, masking invalid flattened pixels
    int g = lane >> 2, t = lane & 3;
    #pragma unroll
    for (int mt = 0; mt < 2; mt++) {
        int q0 = p0 + wm * 32 + mt * 16 + g;       // rows g and g+8
        int q1 = q0 + 8;
        int mq0 = q0 / HPP, nq0 = q0 % HPP;
        int mq1 = q1 / HPP, nq1 = q1 % HPP;
        bool v0 = (mq0 < HP) && (nq0 < HP);
        bool v1 = (mq1 < HP) && (nq1 < HP);
        #pragma unroll
        for (int nt = 0; nt < 8; nt++) {
            int oc = wn * 64 + nt * 8 + t * 2;
            float bi0 = bias[oc], bi1 = bias[oc + 1];
            float* base0 = g_yc + (size_t)(b * CC + oc) * HP * HP;
            float* base1 = g_yc + (size_t)(b * CC + oc + 1) * HP * HP;
            if (v0) {
                base0[mq0 * HP + nq0] = acc[mt][nt][0] + bi0;
                base1[mq0 * HP + nq0] = acc[mt][nt][1] + bi1;
            }
            if (v1) {
                base0[mq1 * HP + nq1] = acc[mt][nt][2] + bi0;
                base1[mq1 * HP + nq1] = acc[mt][nt][3] + bi1;
            }
        }
    }
}

// ---------------- group norms -------------------------------------------------
__global__ void norm_x_kernel() {
    int idx = blockIdx.x * 256 + threadIdx.x;
    if (idx >= BB * NG * HS * HS) return;
    int px = idx % (HS * HS);
    int bg = idx / (HS * HS);
    int b = bg >> 2, g = bg & 3;
    const float* p = g_xs + ((size_t)b * CC + g * CG) * HS * HS + px;
    float s = 0.f;
    #pragma unroll
    for (int c = 0; c < CG; c++) { float v = p[(size_t)c * HS * HS]; s = fmaf(v, v, s); }
    g_nx[idx] = fmaxf(sqrtf(s), EPSV);
}

__global__ void norm_y_kernel() {
    int idx = blockIdx.x * 256 + threadIdx.x;
    if (idx >= BB * NG * HP * HP) return;
    int px = idx % (HP * HP);
    int bg = idx / (HP * HP);
    int b = bg >> 2, g = bg & 3;
    const float* p = g_yc + ((size_t)b * CC + g * CG) * HP * HP + px;
    float s = 0.f;
    #pragma unroll
    for (int c = 0; c < CG; c++) { float v = p[(size_t)c * HP * HP]; s = fmaf(v, v, s); }
    g_ny[idx] = sqrtf(s);
}

// ---------------- 81-offset correlation ----------------------------------------
#define CORR_SY (CG * 16 * 40)
#define CORR_SN (16 * 40)
#define CORR_SMEM ((CORR_SY + CORR_SN) * 4)

__global__ void corr_kernel(float* __restrict__ out) {
    extern __shared__ float smc[];
    float* sy = smc;
    float* sn = smc + CORR_SY;

    int bg = blockIdx.z;
    int b  = bg >> 2, g = bg & 3;
    int i0 = blockIdx.y * 8;
    int j0 = blockIdx.x * 32;
    int tid = threadIdx.x;
    int tj = tid & 31, ti = tid >> 5;

    const float* ycb = g_yc + ((size_t)b * CC + g * CG) * HP * HP;
    for (int e = tid; e < CG * 16 * 40; e += 256) {
        int col = e % 40;
        int row = (e / 40) % 16;
        int c   = e / (16 * 40);
        sy[e] = ycb[(size_t)c * HP * HP + (i0 + row) * HP + (j0 + col)];
    }
    const float* nyb = g_ny + (size_t)bg * HP * HP;
    for (int e = tid; e < 16 * 40; e += 256) {
        int col = e % 40, row = e / 40;
        sn[e] = 1.0f / fmaxf(nyb[(i0 + row) * HP + (j0 + col)], EPSV);
    }
    __syncthreads();

    float xr[CG];
    const float* xsb = g_xs + ((size_t)b * CC + g * CG) * HS * HS
                            + (i0 + ti) * HS + (j0 + tj);
    #pragma unroll
    for (int c = 0; c < CG; c++) xr[c] = xsb[(size_t)c * HS * HS];

    float inx = 1.0f / g_nx[(size_t)bg * HS * HS + (i0 + ti) * HS + (j0 + tj)];
    float* outp = out + (size_t)bg * NOFF * HS * HS + (i0 + ti) * HS + (j0 + tj);

    #pragma unroll 1
    for (int oi = 0; oi < 9; oi++) {
        #pragma unroll 1
        for (int oj = 0; oj < 9; oj++) {
            float a = 0.f;
            int base = (ti + oi) * 40 + tj + oj;
            #pragma unroll
            for (int c = 0; c < CG; c++)
                a = fmaf(xr[c], sy[c * (16 * 40) + base], a);
            outp[(size_t)(oi * 9 + oj) * (HS * HS)] = a * inx * sn[base];
        }
    }
}

// ---------------- launcher ------------------------------------------------------
extern "C" void kernel_launch(void* const* d_in, const int* in_sizes, int n_in,
                              void* d_out, int out_size) {
    const float* x     = (const float*)d_in[0];
    const float* y     = (const float*)d_in[1];
    const float* Wt    = (const float*)d_in[2];
    const float* bconv = (const float*)d_in[3];
    float* out = (float*)d_out;

    cudaFuncSetAttribute(conv_mma_kernel,
                         cudaFuncAttributeMaxDynamicSharedMemorySize, CONV_SMEM);
    cudaFuncSetAttribute(corr_kernel,
                         cudaFuncAttributeMaxDynamicSharedMemorySize, CORR_SMEM);

    downsample_x_kernel<<<(BB*CC*HS*HS) / 256, 256>>>(x);
    make_P_kernel<<<(BB*CC*PROW + 255) / 256, 256>>>(y);
    prep_w_kernel<<<(8*CC*144 + 255) / 256, 256>>>(Wt);
    conv_mma_kernel<<<dim3(147, BB), 256, CONV_SMEM>>>(bconv);
    norm_x_kernel<<<(BB*NG*HS*HS + 255) / 256, 256>>>();
    norm_y_kernel<<<(BB*NG*HP*HP + 255) / 256, 256>>>();
    corr_kernel<<<dim3(4, 16, BB * NG), 256, CORR_SMEM>>>(out);
}